// round 6
// baseline (speedup 1.0000x reference)
#include <cuda_runtime.h>
#include <math.h>

#define SS 256
#define BB 64
#define HH 512
#define EE 300
#define TT 10
#define G4 2048   // 4*H

// ---------------- scratch (static device memory; no allocations) ----------------
__device__ float g_xw_f[SS * BB * G4];       // fwd input projections (134 MB)
__device__ float g_xw_b[SS * BB * G4];       // bwd input projections (134 MB)
__device__ float g_h[SS][BB][2 * HH];        // h outputs; ALSO the recurrent carry (67 MB)
__device__ float g_c[2][HH][BB];             // c carry [dir][j][b]
__device__ float g_feats[BB][SS][TT];        // emissions

__device__ __forceinline__ float sigmf(float x) { return 1.0f / (1.0f + expf(-x)); }

// ---- packed f32x2 helpers (FFMA2 path: 2 fp32 FMAs per instruction, bit-exact) ----
__device__ __forceinline__ unsigned long long pack2(float lo, float hi) {
    unsigned long long r;
    asm("mov.b64 %0, {%1, %2};" : "=l"(r) : "f"(lo), "f"(hi));
    return r;
}
__device__ __forceinline__ void fma2(unsigned long long& d, unsigned long long a, unsigned long long b) {
    asm("fma.rn.f32x2 %0, %1, %2, %0;" : "+l"(d) : "l"(a), "l"(b));
}
__device__ __forceinline__ float2 unpack2(unsigned long long v) {
    float lo, hi;
    asm("mov.b64 {%0, %1}, %2;" : "=f"(lo), "=f"(hi) : "l"(v));
    return make_float2(lo, hi);
}

// ---------------- K1: fused embedding gather + input projection GEMM ----------------
// out[m][n] = sum_e emb[tok(m)][e] * wih[n][e] + bias[n]
__global__ __launch_bounds__(256) void k1_proj(
    const int* __restrict__ tokens, const float* __restrict__ emb,
    const float* __restrict__ wih_f, const float* __restrict__ b_f,
    const float* __restrict__ wih_b, const float* __restrict__ b_b)
{
    __shared__ float As[20][68];   // [k][m-local]
    __shared__ float Bs[20][68];   // [k][n-local]

    const int tid = threadIdx.x;
    const int tx = tid & 15, ty = tid >> 4;
    const int n0 = blockIdx.x * 64;
    const int m0 = blockIdx.y * 64;

    const int arow = tid >> 2;            // 0..63
    const int akk  = (tid & 3) * 5;       // 0,5,10,15
    const int m_g  = m0 + arow;
    const int s_g  = m_g >> 6, b_g = m_g & 63;
    int tok = tokens[b_g * SS + s_g];
    if (tok < 0 || tok >= 30000) tok = 0;
    const float* asrc = emb + (long)tok * EE;

    const int bg = n0 + arow;
    const float* wsrc = (bg < G4) ? (wih_f + (long)bg * EE)
                                  : (wih_b + (long)(bg - G4) * EE);

    // accp[p][j]: packed pair of rows (ty*4+2p, ty*4+2p+1), column tx*4+j
    unsigned long long accp[2][4] = {};

    for (int kt = 0; kt < 15; ++kt) {     // K = 300 = 15 * 20
        const int k0 = kt * 20;
#pragma unroll
        for (int l = 0; l < 5; l++) As[akk + l][arow] = asrc[k0 + akk + l];
#pragma unroll
        for (int l = 0; l < 5; l++) Bs[akk + l][arow] = wsrc[k0 + akk + l];
        __syncthreads();
#pragma unroll
        for (int k = 0; k < 20; k++) {
            ulonglong2 ap = *(const ulonglong2*)&As[k][ty * 4];   // (a0,a1),(a2,a3)
            float4 bv = *(const float4*)&Bs[k][tx * 4];
            unsigned long long bp0 = pack2(bv.x, bv.x);
            unsigned long long bp1 = pack2(bv.y, bv.y);
            unsigned long long bp2 = pack2(bv.z, bv.z);
            unsigned long long bp3 = pack2(bv.w, bv.w);
            fma2(accp[0][0], ap.x, bp0); fma2(accp[0][1], ap.x, bp1);
            fma2(accp[0][2], ap.x, bp2); fma2(accp[0][3], ap.x, bp3);
            fma2(accp[1][0], ap.y, bp0); fma2(accp[1][1], ap.y, bp1);
            fma2(accp[1][2], ap.y, bp2); fma2(accp[1][3], ap.y, bp3);
        }
        __syncthreads();
    }

    // coalesced float4 epilogue
    const int g0  = n0 + tx * 4;
    const int dir = g0 >> 11;
    const int gl0 = g0 & 2047;
    const float* bias = dir ? b_b : b_f;
    float* __restrict__ xw = dir ? g_xw_b : g_xw_f;
    const float bx = bias[gl0 + 0], by = bias[gl0 + 1], bz = bias[gl0 + 2], bw = bias[gl0 + 3];
#pragma unroll
    for (int p = 0; p < 2; p++) {
        float2 r0 = unpack2(accp[p][0]);
        float2 r1 = unpack2(accp[p][1]);
        float2 r2 = unpack2(accp[p][2]);
        float2 r3 = unpack2(accp[p][3]);
        {
            const int mm = m0 + ty * 4 + 2 * p;
            const int s2 = mm >> 6, b2 = mm & 63;
            *(float4*)&xw[(long)(s2 * BB + b2) * G4 + gl0] =
                make_float4(r0.x + bx, r1.x + by, r2.x + bz, r3.x + bw);
        }
        {
            const int mm = m0 + ty * 4 + 2 * p + 1;
            const int s2 = mm >> 6, b2 = mm & 63;
            *(float4*)&xw[(long)(s2 * BB + b2) * G4 + gl0] =
                make_float4(r0.y + bx, r1.y + by, r2.y + bz, r3.y + bw);
        }
    }
}

// ---------------- K2: one LSTM time step (both directions), f32x2 inner ----------------
// grid (128, 2): blockIdx.y = dir, blockIdx.x = slice of 4 hidden units (16 gate rows).
// 2 CTAs/SM. Thread (tu, tb2) owns unit slice*4+tu for batches (2*tb2, 2*tb2+1):
// the i/f/g/o accumulators are packed f32x2 over the batch pair; cell update is
// thread-local. Carry h is read from g_h[sprev] (mask monotonicity => exact).
__global__ __launch_bounds__(128, 2) void k2_step(
    const float* __restrict__ whh_f, const float* __restrict__ whh_b,
    const int* __restrict__ lengths, int sf, int sb, int first)
{
    const int dir   = blockIdx.y;
    const int s     = dir ? sb : sf;
    const int slice = blockIdx.x;        // 0..127
    const float* __restrict__ whh = dir ? whh_b : whh_f;
    const float* __restrict__ xw  = dir ? g_xw_b : g_xw_f;

    __shared__ float wsd[64][36];   // [k][u*8 + q*2 + {0,1}] weight, DUPLICATED per pair
    __shared__ float hs[64][68];    // [k][b]

    const int tid = threadIdx.x;
    const int tu  = tid & 3;        // local unit
    const int tb2 = tid >> 2;       // batch pair 0..31
    const int b0 = 2 * tb2, b1 = b0 + 1;
    const int uj = slice * 4 + tu;  // global hidden unit

    const int len0 = lengths[b0];
    const int len1 = lengths[b1];

    // prefetch input-projection gates (independent of h)
    float xwv[4][2];
    {
        const long base0 = (long)(s * BB + b0) * G4 + uj;
        const long base1 = (long)(s * BB + b1) * G4 + uj;
#pragma unroll
        for (int q = 0; q < 4; q++) {
            xwv[q][0] = __ldg(&xw[base0 + q * HH]);
            xwv[q][1] = __ldg(&xw[base1 + q * HH]);
        }
    }

    unsigned long long acc[4] = {0ull, 0ull, 0ull, 0ull};   // i,f,g,o packed (b0,b1)

    if (!first) {
        const int sprev = dir ? (s + 1) : (s - 1);
        const float* __restrict__ hsrc = &g_h[sprev][0][dir * HH];   // b-stride 2*HH

        // load assignments
        const int hb = tid >> 1;             // batch row 0..63
        const int hk = (tid & 1) * 32;       // k offset within tile
        const int wrow = tid >> 3;           // 0..15 -> (q = wrow>>2, u = wrow&3)
        const int wq = wrow >> 2, wu = wrow & 3;
        const long wbase = (long)(wq * HH + slice * 4 + wu) * HH;
        const int wk = (tid & 7) * 8;
        const int wcol = wu * 8 + wq * 2;

        for (int kt = 0; kt < 8; ++kt) {     // K = 512 = 8 * 64
            const int k0 = kt * 64;
            // hs tile: hs[k][b] <- hsrc[b*2H + k]
#pragma unroll
            for (int l = 0; l < 8; l++) {
                float4 v = *(const float4*)&hsrc[hb * (2 * HH) + k0 + hk + l * 4];
                const int kk = hk + l * 4;
                hs[kk + 0][hb] = v.x; hs[kk + 1][hb] = v.y;
                hs[kk + 2][hb] = v.z; hs[kk + 3][hb] = v.w;
            }
            // wsd tile: duplicated weight pairs
            {
                float4 v0 = *(const float4*)&whh[wbase + k0 + wk];
                float4 v1 = *(const float4*)&whh[wbase + k0 + wk + 4];
                wsd[wk + 0][wcol] = v0.x; wsd[wk + 0][wcol + 1] = v0.x;
                wsd[wk + 1][wcol] = v0.y; wsd[wk + 1][wcol + 1] = v0.y;
                wsd[wk + 2][wcol] = v0.z; wsd[wk + 2][wcol + 1] = v0.z;
                wsd[wk + 3][wcol] = v0.w; wsd[wk + 3][wcol + 1] = v0.w;
                wsd[wk + 4][wcol] = v1.x; wsd[wk + 4][wcol + 1] = v1.x;
                wsd[wk + 5][wcol] = v1.y; wsd[wk + 5][wcol + 1] = v1.y;
                wsd[wk + 6][wcol] = v1.z; wsd[wk + 6][wcol + 1] = v1.z;
                wsd[wk + 7][wcol] = v1.w; wsd[wk + 7][wcol + 1] = v1.w;
            }
            __syncthreads();
#pragma unroll
            for (int k = 0; k < 64; k++) {
                ulonglong2 wa = *(const ulonglong2*)&wsd[k][tu * 8];       // (i,i),(f,f)
                ulonglong2 wb = *(const ulonglong2*)&wsd[k][tu * 8 + 4];   // (g,g),(o,o)
                unsigned long long hp = *(const unsigned long long*)&hs[k][b0];
                fma2(acc[0], wa.x, hp);
                fma2(acc[1], wa.y, hp);
                fma2(acc[2], wb.x, hp);
                fma2(acc[3], wb.y, hp);
            }
            __syncthreads();
        }
    }

    // cell update (thread-local)
    const float2 ai = unpack2(acc[0]);
    const float2 af = unpack2(acc[1]);
    const float2 ag = unpack2(acc[2]);
    const float2 ao = unpack2(acc[3]);

    const float i0 = ai.x + xwv[0][0], f0 = af.x + xwv[1][0];
    const float g0 = ag.x + xwv[2][0], o0 = ao.x + xwv[3][0];
    const float i1 = ai.y + xwv[0][1], f1 = af.y + xwv[1][1];
    const float g1 = ag.y + xwv[2][1], o1 = ao.y + xwv[3][1];

    const float c_old0 = first ? 0.f : g_c[dir][uj][b0];
    const float c_old1 = first ? 0.f : g_c[dir][uj][b1];

    const float cn0 = sigmf(f0) * c_old0 + sigmf(i0) * tanhf(g0);
    const float hn0 = sigmf(o0) * tanhf(cn0);
    const float cn1 = sigmf(f1) * c_old1 + sigmf(i1) * tanhf(g1);
    const float hn1 = sigmf(o1) * tanhf(cn1);

    const bool m0k = s < len0, m1k = s < len1;
    g_c[dir][uj][b0] = m0k ? cn0 : c_old0;
    g_c[dir][uj][b1] = m1k ? cn1 : c_old1;
    g_h[s][b0][dir * HH + uj] = m0k ? hn0 : 0.f;
    g_h[s][b1][dir * HH + uj] = m1k ? hn1 : 0.f;
}

// ---------------- K3: emissions feats = h @ w_out^T + b_out ----------------
__global__ __launch_bounds__(256) void k3_feats(
    const float* __restrict__ w_out, const float* __restrict__ b_out)
{
    __shared__ float ws[TT * 1024];
    for (int i = threadIdx.x; i < TT * 1024; i += 256) ws[i] = w_out[i];
    __syncthreads();

    const int widx = blockIdx.x * 8 + (threadIdx.x >> 5);
    const int lane = threadIdx.x & 31;
    const int s = widx >> 6, b = widx & 63;
    const float* hrow = &g_h[s][b][0];

    float acc[TT];
#pragma unroll
    for (int t = 0; t < TT; t++) acc[t] = 0.0f;

#pragma unroll 4
    for (int i = 0; i < 32; i++) {
        const int k = lane + i * 32;
        const float hv = hrow[k];
#pragma unroll
        for (int t = 0; t < TT; t++) acc[t] += hv * ws[t * 1024 + k];
    }
#pragma unroll
    for (int t = 0; t < TT; t++) {
        float v = acc[t];
        v += __shfl_xor_sync(0xffffffffu, v, 16);
        v += __shfl_xor_sync(0xffffffffu, v, 8);
        v += __shfl_xor_sync(0xffffffffu, v, 4);
        v += __shfl_xor_sync(0xffffffffu, v, 2);
        v += __shfl_xor_sync(0xffffffffu, v, 1);
        if (lane == t) g_feats[b][s][t] = v + b_out[t];
    }
}

// ---------------- K4: Viterbi decode + backtrace (one warp per batch) ----------------
// Output written as float32 (harness __output__ dtype) — tags exactly representable.
__global__ __launch_bounds__(32) void k4_viterbi(
    const float* __restrict__ start_t, const float* __restrict__ end_t,
    const float* __restrict__ trans, const int* __restrict__ lengths,
    float* __restrict__ out)
{
    const int b = blockIdx.x;
    const int lane = threadIdx.x;
    __shared__ float fe[SS][TT];
    __shared__ float tr[TT][TT];
    __shared__ float sc[TT];
    __shared__ unsigned char bp[SS][TT];

    for (int i = lane; i < SS * TT; i += 32)
        ((float*)fe)[i] = ((const float*)g_feats[b])[i];
    for (int i = lane; i < TT * TT; i += 32)
        ((float*)tr)[i] = trans[i];
    int len = lengths[b];
    if (len < 0) len = 0; if (len > SS) len = SS;
    __syncwarp();
    if (lane < TT) sc[lane] = start_t[lane] + fe[0][lane];
    __syncwarp();

    for (int s = 1; s < SS; ++s) {
        float best = -1e30f; int arg = 0;
        if (lane < TT) {
#pragma unroll
            for (int i = 0; i < TT; i++) {
                const float c = sc[i] + tr[i][lane];
                if (c > best) { best = c; arg = i; }   // first-max, matches jnp.argmax
            }
        }
        __syncwarp();
        if (lane < TT) {
            if (s < len) { sc[lane] = best + fe[s][lane]; bp[s][lane] = (unsigned char)arg; }
            else         { bp[s][lane] = (unsigned char)lane; }
        }
        __syncwarp();
    }

    if (lane == 0) {
        float bestv = -1e30f; int last = 0;
        for (int j = 0; j < TT; j++) {
            const float v = sc[j] + end_t[j];
            if (v > bestv) { bestv = v; last = j; }
        }
        int cur = last;
        for (int s = SS - 1; s >= 1; --s) {
            out[b * SS + s] = (float)((s < len) ? cur : 0);
            cur = bp[s][cur];
        }
        out[b * SS + 0] = (float)cur;
    }
}

// ---------------- host ----------------
static int find_slot(const int* sz, int n, int want, int which, int fallback) {
    int seen = 0;
    for (int i = 0; i < n; i++)
        if (sz[i] == want) { if (seen == which) return i; seen++; }
    return fallback;
}

extern "C" void kernel_launch(void* const* d_in, const int* in_sizes, int n_in,
                              void* d_out, int out_size)
{
    const int i_tok  = find_slot(in_sizes, n_in, SS * BB,      0, 0);
    const int i_len  = find_slot(in_sizes, n_in, BB,           0, 1);
    const int i_emb  = find_slot(in_sizes, n_in, 30000 * EE,   0, 2);
    const int i_wif  = find_slot(in_sizes, n_in, G4 * EE,      0, 3);
    const int i_whf  = find_slot(in_sizes, n_in, G4 * HH,      0, 4);
    const int i_bf   = find_slot(in_sizes, n_in, G4,           0, 5);
    const int i_wib  = find_slot(in_sizes, n_in, G4 * EE,      1, 6);
    const int i_whb  = find_slot(in_sizes, n_in, G4 * HH,      1, 7);
    const int i_bb   = find_slot(in_sizes, n_in, G4,           1, 8);
    const int i_wout = find_slot(in_sizes, n_in, TT * 2 * HH,  0, 9);
    const int i_bout = find_slot(in_sizes, n_in, TT,           0, 10);
    const int i_st   = find_slot(in_sizes, n_in, TT,           1, 11);
    const int i_en   = find_slot(in_sizes, n_in, TT,           2, 12);
    const int i_tr   = find_slot(in_sizes, n_in, TT * TT,      0, 13);

    const int*   tokens  = (const int*)  d_in[i_tok];
    const int*   lens    = (const int*)  d_in[i_len];
    const float* emb     = (const float*)d_in[i_emb];
    const float* wih_f   = (const float*)d_in[i_wif];
    const float* whh_f   = (const float*)d_in[i_whf];
    const float* b_f     = (const float*)d_in[i_bf];
    const float* wih_b   = (const float*)d_in[i_wib];
    const float* whh_b   = (const float*)d_in[i_whb];
    const float* b_b     = (const float*)d_in[i_bb];
    const float* w_out   = (const float*)d_in[i_wout];
    const float* b_out   = (const float*)d_in[i_bout];
    const float* start_t = (const float*)d_in[i_st];
    const float* end_t   = (const float*)d_in[i_en];
    const float* trans   = (const float*)d_in[i_tr];
    float* out = (float*)d_out;

    k1_proj<<<dim3(64, 256), 256>>>(tokens, emb, wih_f, b_f, wih_b, b_b);
    for (int t = 0; t < SS; ++t)
        k2_step<<<dim3(128, 2), 128>>>(whh_f, whh_b, lens, t, SS - 1 - t, t == 0);
    k3_feats<<<2048, 256>>>(w_out, b_out);
    k4_viterbi<<<64, 32>>>(start_t, end_t, trans, lens, out);
}

// round 7
// speedup vs baseline: 1.3681x; 1.3681x over previous
#include <cuda_runtime.h>
#include <math.h>

#define SS 256
#define BB 64
#define HH 512
#define EE 300
#define TT 10
#define G4 2048   // 4*H

// ---------------- scratch (static device memory; no allocations) ----------------
__device__ float g_xw_f[SS * BB * G4];       // fwd input projections (134 MB)
__device__ float g_xw_b[SS * BB * G4];       // bwd input projections (134 MB)
__device__ float g_h[SS][BB][2 * HH];        // h outputs for K3 (67 MB)
__device__ float g_ht[2][2][HH][BB];         // [dir][parity][unit][b] transposed carry
__device__ float g_c[2][HH][BB];             // c carry [dir][j][b]
__device__ float g_wdup[2][HH][4096];        // permuted+duplicated whh (16 MB)
__device__ float g_feats[BB][SS][TT];        // emissions

__device__ __forceinline__ float sigmf(float x) { return 1.0f / (1.0f + expf(-x)); }

// ---- packed f32x2 helpers (FFMA2: 2 independent fp32 FMAs, bit-exact) ----
__device__ __forceinline__ unsigned long long pack2(float lo, float hi) {
    unsigned long long r;
    asm("mov.b64 %0, {%1, %2};" : "=l"(r) : "f"(lo), "f"(hi));
    return r;
}
__device__ __forceinline__ void fma2(unsigned long long& d, unsigned long long a, unsigned long long b) {
    asm("fma.rn.f32x2 %0, %1, %2, %0;" : "+l"(d) : "l"(a), "l"(b));
}
__device__ __forceinline__ float2 unpack2(unsigned long long v) {
    float lo, hi;
    asm("mov.b64 {%0, %1}, %2;" : "=f"(lo), "=f"(hi) : "l"(v));
    return make_float2(lo, hi);
}

// ---------------- K0p: permute + duplicate recurrent weights ----------------
// g_wdup[d][k][u*8 + q*2 + {0,1}] = whh_d[q*HH + u][k]
__global__ void k0_prep(const float* __restrict__ whh_f, const float* __restrict__ whh_b) {
    const int d = blockIdx.x;
    const int k = blockIdx.y;
    const int u = threadIdx.x;    // 0..511
    const float* w = d ? whh_b : whh_f;
    float* o = &g_wdup[d][k][u * 8];
#pragma unroll
    for (int q = 0; q < 4; q++) {
        const float v = w[(q * HH + u) * HH + k];
        o[q * 2] = v; o[q * 2 + 1] = v;
    }
}

// ---------------- K1: fused embedding gather + input projection GEMM ----------------
__global__ __launch_bounds__(256) void k1_proj(
    const int* __restrict__ tokens, const float* __restrict__ emb,
    const float* __restrict__ wih_f, const float* __restrict__ b_f,
    const float* __restrict__ wih_b, const float* __restrict__ b_b)
{
    __shared__ float As[20][68];   // [k][m-local]
    __shared__ float Bs[20][68];   // [k][n-local]

    const int tid = threadIdx.x;
    const int tx = tid & 15, ty = tid >> 4;
    const int n0 = blockIdx.x * 64;
    const int m0 = blockIdx.y * 64;

    const int arow = tid >> 2;            // 0..63
    const int akk  = (tid & 3) * 5;       // 0,5,10,15
    const int m_g  = m0 + arow;
    const int s_g  = m_g >> 6, b_g = m_g & 63;
    int tok = tokens[b_g * SS + s_g];
    if (tok < 0 || tok >= 30000) tok = 0;
    const float* asrc = emb + (long)tok * EE;

    const int bg = n0 + arow;
    const float* wsrc = (bg < G4) ? (wih_f + (long)bg * EE)
                                  : (wih_b + (long)(bg - G4) * EE);

    unsigned long long accp[2][4] = {};

    for (int kt = 0; kt < 15; ++kt) {     // K = 300 = 15 * 20
        const int k0 = kt * 20;
#pragma unroll
        for (int l = 0; l < 5; l++) As[akk + l][arow] = asrc[k0 + akk + l];
#pragma unroll
        for (int l = 0; l < 5; l++) Bs[akk + l][arow] = wsrc[k0 + akk + l];
        __syncthreads();
#pragma unroll
        for (int k = 0; k < 20; k++) {
            ulonglong2 ap = *(const ulonglong2*)&As[k][ty * 4];
            float4 bv = *(const float4*)&Bs[k][tx * 4];
            unsigned long long bp0 = pack2(bv.x, bv.x);
            unsigned long long bp1 = pack2(bv.y, bv.y);
            unsigned long long bp2 = pack2(bv.z, bv.z);
            unsigned long long bp3 = pack2(bv.w, bv.w);
            fma2(accp[0][0], ap.x, bp0); fma2(accp[0][1], ap.x, bp1);
            fma2(accp[0][2], ap.x, bp2); fma2(accp[0][3], ap.x, bp3);
            fma2(accp[1][0], ap.y, bp0); fma2(accp[1][1], ap.y, bp1);
            fma2(accp[1][2], ap.y, bp2); fma2(accp[1][3], ap.y, bp3);
        }
        __syncthreads();
    }

    const int g0  = n0 + tx * 4;
    const int dir = g0 >> 11;
    const int gl0 = g0 & 2047;
    const float* bias = dir ? b_b : b_f;
    float* __restrict__ xw = dir ? g_xw_b : g_xw_f;
    const float bx = bias[gl0 + 0], by = bias[gl0 + 1], bz = bias[gl0 + 2], bw = bias[gl0 + 3];
#pragma unroll
    for (int p = 0; p < 2; p++) {
        float2 r0 = unpack2(accp[p][0]);
        float2 r1 = unpack2(accp[p][1]);
        float2 r2 = unpack2(accp[p][2]);
        float2 r3 = unpack2(accp[p][3]);
        {
            const int mm = m0 + ty * 4 + 2 * p;
            const int s2 = mm >> 6, b2 = mm & 63;
            *(float4*)&xw[(long)(s2 * BB + b2) * G4 + gl0] =
                make_float4(r0.x + bx, r1.x + by, r2.x + bz, r3.x + bw);
        }
        {
            const int mm = m0 + ty * 4 + 2 * p + 1;
            const int s2 = mm >> 6, b2 = mm & 63;
            *(float4*)&xw[(long)(s2 * BB + b2) * G4 + gl0] =
                make_float4(r0.y + bx, r1.y + by, r2.y + bz, r3.y + bw);
        }
    }
}

// ---------------- K2: one LSTM time step, crossbar-lean f32x2 ----------------
// grid (128, 2): blockIdx.y = dir, blockIdx.x = slice of 4 hidden units.
// Thread (tx = unit-in-slice, tb = batch pair). All smem staging is float4
// copies from pre-transposed globals (g_wdup, g_ht). Inner loop: 3 LDS + 4 FFMA2.
__global__ __launch_bounds__(128, 2) void k2_step(
    const int* __restrict__ lengths, int t)
{
    const int dir   = blockIdx.y;
    const int s     = dir ? (SS - 1 - t) : t;
    const int slice = blockIdx.x;        // 0..127
    const float* __restrict__ xw = dir ? g_xw_b : g_xw_f;

    __shared__ float sw[64][32];    // [k][u*8 + q*2 + {0,1}] duplicated weights
    __shared__ float hs[64][68];    // [k][b]

    const int tid = threadIdx.x;
    const int tx = tid & 3;         // unit in slice
    const int tb = tid >> 2;        // batch pair 0..31
    const int b0 = 2 * tb, b1 = b0 + 1;
    const int uj = slice * 4 + tx;  // global hidden unit

    const int len0 = lengths[b0];
    const int len1 = lengths[b1];

    // prefetch input-projection gates (independent of h)
    float xwv[4][2];
    {
        const long base0 = (long)(s * BB + b0) * G4 + uj;
        const long base1 = (long)(s * BB + b1) * G4 + uj;
#pragma unroll
        for (int q = 0; q < 4; q++) {
            xwv[q][0] = __ldg(&xw[base0 + q * HH]);
            xwv[q][1] = __ldg(&xw[base1 + q * HH]);
        }
    }

    unsigned long long acc[4] = {0ull, 0ull, 0ull, 0ull};   // i,f,g,o over (b0,b1)

    if (t > 0) {
        const float* __restrict__ hsrc = &g_ht[dir][(t & 1) ^ 1][0][0];   // [unit][b]
        const float* __restrict__ wsrc = &g_wdup[dir][0][slice * 32];     // row stride 4096

        for (int kt = 0; kt < 8; ++kt) {     // K = 512 = 8 * 64
            const int k0 = kt * 64;
            // hs tile: 64 units x 64 b = 1024 float4, straight copy
#pragma unroll
            for (int i = 0; i < 8; i++) {
                const int idx = tid + i * 128;
                const int r = idx >> 4, c = (idx & 15) * 4;
                *(float4*)&hs[r][c] = *(const float4*)&hsrc[(k0 + r) * BB + c];
            }
            // sw tile: 64 x 32 = 512 float4, straight copy
#pragma unroll
            for (int i = 0; i < 4; i++) {
                const int idx = tid + i * 128;
                const int r = idx >> 3, c = (idx & 7) * 4;
                *(float4*)&sw[r][c] = *(const float4*)&wsrc[(long)(k0 + r) * 4096 + c];
            }
            __syncthreads();
#pragma unroll
            for (int k = 0; k < 64; k++) {
                ulonglong2 wa = *(const ulonglong2*)&sw[k][tx * 8];       // (i,i),(f,f)
                ulonglong2 wb = *(const ulonglong2*)&sw[k][tx * 8 + 4];   // (g,g),(o,o)
                unsigned long long hp = *(const unsigned long long*)&hs[k][b0];
                fma2(acc[0], wa.x, hp);
                fma2(acc[1], wa.y, hp);
                fma2(acc[2], wb.x, hp);
                fma2(acc[3], wb.y, hp);
            }
            __syncthreads();
        }
    }

    // cell update (thread-local)
    const float2 ai = unpack2(acc[0]);
    const float2 af = unpack2(acc[1]);
    const float2 ag = unpack2(acc[2]);
    const float2 ao = unpack2(acc[3]);

    const float i0 = ai.x + xwv[0][0], f0 = af.x + xwv[1][0];
    const float gg0 = ag.x + xwv[2][0], o0 = ao.x + xwv[3][0];
    const float i1 = ai.y + xwv[0][1], f1 = af.y + xwv[1][1];
    const float gg1 = ag.y + xwv[2][1], o1 = ao.y + xwv[3][1];

    const float c_old0 = (t == 0) ? 0.f : g_c[dir][uj][b0];
    const float c_old1 = (t == 0) ? 0.f : g_c[dir][uj][b1];

    const float cn0 = sigmf(f0) * c_old0 + sigmf(i0) * tanhf(gg0);
    const float hn0 = sigmf(o0) * tanhf(cn0);
    const float cn1 = sigmf(f1) * c_old1 + sigmf(i1) * tanhf(gg1);
    const float hn1 = sigmf(o1) * tanhf(cn1);

    const bool m0k = s < len0, m1k = s < len1;
    const float ho0 = m0k ? hn0 : 0.f;
    const float ho1 = m1k ? hn1 : 0.f;
    g_c[dir][uj][b0] = m0k ? cn0 : c_old0;
    g_c[dir][uj][b1] = m1k ? cn1 : c_old1;
    g_ht[dir][t & 1][uj][b0] = ho0;           // carry (masked output; exact, see R2/R4)
    g_ht[dir][t & 1][uj][b1] = ho1;
    g_h[s][b0][dir * HH + uj] = ho0;          // for K3
    g_h[s][b1][dir * HH + uj] = ho1;
}

// ---------------- K3: emissions feats = h @ w_out^T + b_out ----------------
__global__ __launch_bounds__(256) void k3_feats(
    const float* __restrict__ w_out, const float* __restrict__ b_out)
{
    __shared__ float ws[TT * 1024];
    for (int i = threadIdx.x; i < TT * 1024; i += 256) ws[i] = w_out[i];
    __syncthreads();

    const int widx = blockIdx.x * 8 + (threadIdx.x >> 5);
    const int lane = threadIdx.x & 31;
    const int s = widx >> 6, b = widx & 63;
    const float* hrow = &g_h[s][b][0];

    float acc[TT];
#pragma unroll
    for (int t = 0; t < TT; t++) acc[t] = 0.0f;

#pragma unroll 4
    for (int i = 0; i < 32; i++) {
        const int k = lane + i * 32;
        const float hv = hrow[k];
#pragma unroll
        for (int t = 0; t < TT; t++) acc[t] += hv * ws[t * 1024 + k];
    }
#pragma unroll
    for (int t = 0; t < TT; t++) {
        float v = acc[t];
        v += __shfl_xor_sync(0xffffffffu, v, 16);
        v += __shfl_xor_sync(0xffffffffu, v, 8);
        v += __shfl_xor_sync(0xffffffffu, v, 4);
        v += __shfl_xor_sync(0xffffffffu, v, 2);
        v += __shfl_xor_sync(0xffffffffu, v, 1);
        if (lane == t) g_feats[b][s][t] = v + b_out[t];
    }
}

// ---------------- K4: Viterbi decode + backtrace (one warp per batch) ----------------
// Output written as float32 (harness __output__ dtype) — tags exactly representable.
__global__ __launch_bounds__(32) void k4_viterbi(
    const float* __restrict__ start_t, const float* __restrict__ end_t,
    const float* __restrict__ trans, const int* __restrict__ lengths,
    float* __restrict__ out)
{
    const int b = blockIdx.x;
    const int lane = threadIdx.x;
    __shared__ float fe[SS][TT];
    __shared__ float tr[TT][TT];
    __shared__ float sc[TT];
    __shared__ unsigned char bp[SS][TT];

    for (int i = lane; i < SS * TT; i += 32)
        ((float*)fe)[i] = ((const float*)g_feats[b])[i];
    for (int i = lane; i < TT * TT; i += 32)
        ((float*)tr)[i] = trans[i];
    int len = lengths[b];
    if (len < 0) len = 0; if (len > SS) len = SS;
    __syncwarp();
    if (lane < TT) sc[lane] = start_t[lane] + fe[0][lane];
    __syncwarp();

    for (int s = 1; s < SS; ++s) {
        float best = -1e30f; int arg = 0;
        if (lane < TT) {
#pragma unroll
            for (int i = 0; i < TT; i++) {
                const float c = sc[i] + tr[i][lane];
                if (c > best) { best = c; arg = i; }   // first-max, matches jnp.argmax
            }
        }
        __syncwarp();
        if (lane < TT) {
            if (s < len) { sc[lane] = best + fe[s][lane]; bp[s][lane] = (unsigned char)arg; }
            else         { bp[s][lane] = (unsigned char)lane; }
        }
        __syncwarp();
    }

    if (lane == 0) {
        float bestv = -1e30f; int last = 0;
        for (int j = 0; j < TT; j++) {
            const float v = sc[j] + end_t[j];
            if (v > bestv) { bestv = v; last = j; }
        }
        int cur = last;
        for (int s = SS - 1; s >= 1; --s) {
            out[b * SS + s] = (float)((s < len) ? cur : 0);
            cur = bp[s][cur];
        }
        out[b * SS + 0] = (float)cur;
    }
}

// ---------------- host ----------------
static int find_slot(const int* sz, int n, int want, int which, int fallback) {
    int seen = 0;
    for (int i = 0; i < n; i++)
        if (sz[i] == want) { if (seen == which) return i; seen++; }
    return fallback;
}

extern "C" void kernel_launch(void* const* d_in, const int* in_sizes, int n_in,
                              void* d_out, int out_size)
{
    const int i_tok  = find_slot(in_sizes, n_in, SS * BB,      0, 0);
    const int i_len  = find_slot(in_sizes, n_in, BB,           0, 1);
    const int i_emb  = find_slot(in_sizes, n_in, 30000 * EE,   0, 2);
    const int i_wif  = find_slot(in_sizes, n_in, G4 * EE,      0, 3);
    const int i_whf  = find_slot(in_sizes, n_in, G4 * HH,      0, 4);
    const int i_bf   = find_slot(in_sizes, n_in, G4,           0, 5);
    const int i_wib  = find_slot(in_sizes, n_in, G4 * EE,      1, 6);
    const int i_whb  = find_slot(in_sizes, n_in, G4 * HH,      1, 7);
    const int i_bb   = find_slot(in_sizes, n_in, G4,           1, 8);
    const int i_wout = find_slot(in_sizes, n_in, TT * 2 * HH,  0, 9);
    const int i_bout = find_slot(in_sizes, n_in, TT,           0, 10);
    const int i_st   = find_slot(in_sizes, n_in, TT,           1, 11);
    const int i_en   = find_slot(in_sizes, n_in, TT,           2, 12);
    const int i_tr   = find_slot(in_sizes, n_in, TT * TT,      0, 13);

    const int*   tokens  = (const int*)  d_in[i_tok];
    const int*   lens    = (const int*)  d_in[i_len];
    const float* emb     = (const float*)d_in[i_emb];
    const float* wih_f   = (const float*)d_in[i_wif];
    const float* whh_f   = (const float*)d_in[i_whf];
    const float* b_f     = (const float*)d_in[i_bf];
    const float* wih_b   = (const float*)d_in[i_wib];
    const float* whh_b   = (const float*)d_in[i_whb];
    const float* b_b     = (const float*)d_in[i_bb];
    const float* w_out   = (const float*)d_in[i_wout];
    const float* b_out   = (const float*)d_in[i_bout];
    const float* start_t = (const float*)d_in[i_st];
    const float* end_t   = (const float*)d_in[i_en];
    const float* trans   = (const float*)d_in[i_tr];
    float* out = (float*)d_out;

    k0_prep<<<dim3(2, HH), HH>>>(whh_f, whh_b);
    k1_proj<<<dim3(64, 256), 256>>>(tokens, emb, wih_f, b_f, wih_b, b_b);
    for (int t = 0; t < SS; ++t)
        k2_step<<<dim3(128, 2), 128>>>(lens, t);
    k3_feats<<<2048, 256>>>(w_out, b_out);
    k4_viterbi<<<64, 32>>>(start_t, end_t, trans, lens, out);
}